// round 15
// baseline (speedup 1.0000x reference)
#include <cuda_runtime.h>
#include <cuda_fp16.h>
#include <mma.h>
#include <math.h>
#include <stdint.h>

using namespace nvcuda;

#define N_NODES   100000
#define DEG       16
#define IN_DIM    128
#define OUT_DIM   32
#define EPS       1e-8f

// scratch (device globals: no allocation allowed in kernel_launch)
__device__ __half2 g_zh[N_NODES * (OUT_DIM / 2)];   // z rows in fp16 (only copy)

__device__ __forceinline__ float2 h2f(uint32_t u) {
    __half2 h = *reinterpret_cast<__half2*>(&u);
    return __half22float2(h);
}

// ---------------------------------------------------------------------------
// Kernel 1: z = h @ W^T via wmma FP16 (m16n16k16), fp32 accumulate.
// One CTA per 64-row tile (1563 CTAs), 256 threads = 8 warps, 26.1KB smem.
// Norms no longer stored — edge kernel derives them from the fp16 rows.
// ---------------------------------------------------------------------------
#define LDH2 136
#define LDZ  36
#define GEMM_SMEM_BYTES 26112

__global__ __launch_bounds__(256) void gemm_wmma_kernel(
    const float* __restrict__ h, const float* __restrict__ W, int N)
{
    extern __shared__ char smraw[];
    __half* Ws  = reinterpret_cast<__half*>(smraw);           // [32][136]
    __half* hs  = reinterpret_cast<__half*>(smraw + 8704);    // [64][136]
    float*  zsm = reinterpret_cast<float*>(smraw + 8704);     // [64][36] alias

    const int tid  = threadIdx.x;
    const int wid  = tid >> 5;
    const int m0   = (wid & 3) * 16;
    const int n0   = (wid >> 2) * 16;
    const int row0 = blockIdx.x * 64;

    // ---- stage W -> fp16 smem ----
    const float4* W4 = reinterpret_cast<const float4*>(W);
    #pragma unroll
    for (int i = 0; i < 4; i++) {
        int f  = tid + i * 256;
        int n  = f >> 5;
        int k4 = f & 31;
        float4 v = __ldg(&W4[n * 32 + k4]);
        __half2 hx[2] = { __floats2half2_rn(v.x, v.y),
                          __floats2half2_rn(v.z, v.w) };
        *reinterpret_cast<uint2*>(&Ws[n * LDH2 + k4 * 4]) =
            *reinterpret_cast<const uint2*>(hx);
    }

    // ---- load 64-row h tile -> fp16 smem ----
    const float4* h4 = reinterpret_cast<const float4*>(h);
    #pragma unroll
    for (int i = 0; i < 8; i++) {
        int f    = tid + i * 256;
        int r    = f >> 5;
        int k4   = f & 31;
        int grow = row0 + r;
        if (grow >= N) grow = N - 1;
        float4 v = __ldg(&h4[grow * 32 + k4]);
        __half2 hx[2] = { __floats2half2_rn(v.x, v.y),
                          __floats2half2_rn(v.z, v.w) };
        *reinterpret_cast<uint2*>(&hs[r * LDH2 + k4 * 4]) =
            *reinterpret_cast<const uint2*>(hx);
    }
    __syncthreads();

    // ---- wmma: 1 m-tile x 1 n-tile x 8 k-steps per warp ----
    wmma::fragment<wmma::accumulator, 16, 16, 16, float> c0;
    wmma::fill_fragment(c0, 0.0f);
    wmma::fragment<wmma::matrix_a, 16, 16, 16, __half, wmma::row_major> a0;
    wmma::fragment<wmma::matrix_b, 16, 16, 16, __half, wmma::col_major> b0;
    #pragma unroll
    for (int ks = 0; ks < 8; ks++) {
        wmma::load_matrix_sync(a0, &hs[m0 * LDH2 + ks * 16], LDH2);
        wmma::load_matrix_sync(b0, &Ws[n0 * LDH2 + ks * 16], LDH2);
        wmma::mma_sync(c0, a0, b0, c0);
    }
    __syncthreads();

    wmma::store_matrix_sync(&zsm[m0 * LDZ + n0], c0, LDZ, wmma::mem_row_major);
    __syncthreads();

    // ---- epilogue: fp16 z only (coalesced 16B/thread) ----
    int row = tid >> 2;
    int q   = tid & 3;
    float4 z4[2];
    z4[0] = *reinterpret_cast<const float4*>(&zsm[row * LDZ + q * 8]);
    z4[1] = *reinterpret_cast<const float4*>(&zsm[row * LDZ + q * 8 + 4]);
    int grow = row0 + row;
    if (grow < N) {
        __half2 hx[4];
        hx[0] = __floats2half2_rn(z4[0].x, z4[0].y);
        hx[1] = __floats2half2_rn(z4[0].z, z4[0].w);
        hx[2] = __floats2half2_rn(z4[1].x, z4[1].y);
        hx[3] = __floats2half2_rn(z4[1].z, z4[1].w);
        *reinterpret_cast<uint4*>(&g_zh[grow * 16 + q * 4]) =
            *reinterpret_cast<const uint4*>(hx);
    }
}

// ---------------------------------------------------------------------------
// Kernel 2: per-node cosine attention + softmax + weighted aggregation.
// Half-warp per node, parity-split lanes (odd = hl>>3, sub = hl&7).
// Each lane gathers 8 edge-row chunks (uint2, 4 dims). TWO pack-trees over
// the same v data: dot(zs,zd) and ||zs||^2 (src norms derived in-register —
// the 32-wavefront norm scatter is eliminated). ||zd||^2 via 3-shfl butterfly.
// ---------------------------------------------------------------------------
__global__ __launch_bounds__(256) void edge_agg_kernel(
    const float* __restrict__ beta_p, const int* __restrict__ src,
    float* __restrict__ out, int N)
{
    __shared__ float alpha_sm[8][32];

    const int warp_id = (blockIdx.x * blockDim.x + threadIdx.x) >> 5;
    if (warp_id * 2 >= N) return;

    const int w    = threadIdx.x >> 5;
    const int lane = threadIdx.x & 31;
    const int half = lane >> 4;
    const int hl   = lane & 15;
    const int odd  = (hl >> 3) & 1;
    const int sub  = hl & 7;
    int node = warp_id * 2 + half;
    const bool valid = (node < N);
    if (!valid) node = N - 1;

    const unsigned FULL = 0xffffffffu;
    const float beta = __ldg(beta_p);
    const __half* zh = reinterpret_cast<const __half*>(g_zh);

    // own z chunk: dims 4*sub .. 4*sub+3
    uint2 zraw = *reinterpret_cast<const uint2*>(zh + node * 32 + 4 * sub);
    float2 zd0 = h2f(zraw.x);
    float2 zd1 = h2f(zraw.y);

    // dst norm: butterfly over sub bits (lanes 0-7 / 8-15 hold same chunks)
    float ssd = fmaf(zd0.x, zd0.x, fmaf(zd0.y, zd0.y,
                fmaf(zd1.x, zd1.x, zd1.y * zd1.y)));
    ssd += __shfl_xor_sync(FULL, ssd, 1);
    ssd += __shfl_xor_sync(FULL, ssd, 2);
    ssd += __shfl_xor_sync(FULL, ssd, 4);
    const float inorm_d = rsqrtf(ssd);

    // all 16 src indices (uniform int4 loads)
    const int4* sp = reinterpret_cast<const int4*>(src + node * DEG);
    int4 s0 = __ldg(sp + 0);
    int4 s1 = __ldg(sp + 1);
    int4 s2 = __ldg(sp + 2);
    int4 s3 = __ldg(sp + 3);
    int si[DEG] = { s0.x, s0.y, s0.z, s0.w,  s1.x, s1.y, s1.z, s1.w,
                    s2.x, s2.y, s2.z, s2.w,  s3.x, s3.y, s3.z, s3.w };

    // gather order: item k = edge 2*R3[k] + odd  (R3 = 3-bit bit-reverse)
    constexpr int R3[8] = {0,4,2,6,1,5,3,7};
    int se[8];
    #pragma unroll
    for (int k = 0; k < 8; k++) {
        int e = 2 * R3[k];
        se[k] = odd ? si[e + 1] : si[e];
    }

    // gather: 4 dims of one edge per lane per LDG.64
    uint2 v[8];
    #pragma unroll
    for (int k = 0; k < 8; k++)
        v[k] = *reinterpret_cast<const uint2*>(zh + se[k] * 32 + 4 * sub);

    // per-lane partials: dot(zs,zd) and |zs|^2
    float p[8], ps[8];
    #pragma unroll
    for (int k = 0; k < 8; k++) {
        float2 a = h2f(v[k].x);
        float2 b = h2f(v[k].y);
        p[k]  = fmaf(a.x, zd0.x, fmaf(a.y, zd0.y,
                fmaf(b.x, zd1.x, b.y * zd1.y)));
        ps[k] = fmaf(a.x, a.x, fmaf(a.y, a.y,
                fmaf(b.x, b.x, b.y * b.y)));
    }

    const bool c4 = (sub & 4) != 0;
    const bool c2 = (sub & 2) != 0;
    const bool c1 = (sub & 1) != 0;

    // ---- pack-tree #1: dot ----
    float s[4];
    #pragma unroll
    for (int i = 0; i < 4; i++) {
        float a = p[2 * i]     + __shfl_xor_sync(FULL, p[2 * i], 4);
        float b = p[2 * i + 1] + __shfl_xor_sync(FULL, p[2 * i + 1], 4);
        s[i] = c4 ? b : a;
    }
    float q[2];
    #pragma unroll
    for (int i = 0; i < 2; i++) {
        float a = s[2 * i]     + __shfl_xor_sync(FULL, s[2 * i], 2);
        float b = s[2 * i + 1] + __shfl_xor_sync(FULL, s[2 * i + 1], 2);
        q[i] = c2 ? b : a;
    }
    float ra = q[0] + __shfl_xor_sync(FULL, q[0], 1);
    float rb = q[1] + __shfl_xor_sync(FULL, q[1], 1);
    float dotv = c1 ? rb : ra;             // dot of edge 2*sub+odd

    // ---- pack-tree #2: |zs|^2 (same routing) ----
    #pragma unroll
    for (int i = 0; i < 4; i++) {
        float a = ps[2 * i]     + __shfl_xor_sync(FULL, ps[2 * i], 4);
        float b = ps[2 * i + 1] + __shfl_xor_sync(FULL, ps[2 * i + 1], 4);
        s[i] = c4 ? b : a;
    }
    #pragma unroll
    for (int i = 0; i < 2; i++) {
        float a = s[2 * i]     + __shfl_xor_sync(FULL, s[2 * i], 2);
        float b = s[2 * i + 1] + __shfl_xor_sync(FULL, s[2 * i + 1], 2);
        q[i] = c2 ? b : a;
    }
    ra = q[0] + __shfl_xor_sync(FULL, q[0], 1);
    rb = q[1] + __shfl_xor_sync(FULL, q[1], 1);
    float ssv = c1 ? rb : ra;              // |zs|^2 of edge 2*sub+odd

    // softmax weight: exp(beta*cos) (constant cancels; bounded)
    float esc = __expf(beta * (dotv * rsqrtf(ssv) * inorm_d));

    // slot hl = (odd<<3)|sub holds esc of edge 2*sub+odd
    alpha_sm[w][lane] = esc;
    __syncwarp(FULL);

    // read own parity block: slot s holds edge 2s+odd = alpha of v[R3[s]]
    const float4* ap = reinterpret_cast<const float4*>(&alpha_sm[w][lane & 24]);
    float4 A0 = ap[0];
    float4 A1 = ap[1];
    float d = (A0.x + A0.y) + (A0.z + A0.w) + (A1.x + A1.y) + (A1.z + A1.w);

    float o0 = 0.f, o1 = 0.f, o2 = 0.f, o3 = 0.f;
    #define ACC(af, vm) do {                                   \
        float2 va = h2f((vm).x);                               \
        float2 vb = h2f((vm).y);                               \
        o0 = fmaf((af), va.x, o0);  o1 = fmaf((af), va.y, o1); \
        o2 = fmaf((af), vb.x, o2);  o3 = fmaf((af), vb.y, o3); \
    } while (0)
    ACC(A0.x, v[0]);  ACC(A0.y, v[4]);  ACC(A0.z, v[2]);  ACC(A0.w, v[6]);
    ACC(A1.x, v[1]);  ACC(A1.y, v[5]);  ACC(A1.z, v[3]);  ACC(A1.w, v[7]);
    #undef ACC

    // combine parity halves (same sub, other odd)
    o0 += __shfl_xor_sync(FULL, o0, 8);
    o1 += __shfl_xor_sync(FULL, o1, 8);
    o2 += __shfl_xor_sync(FULL, o2, 8);
    o3 += __shfl_xor_sync(FULL, o3, 8);
    float denom = d + __shfl_xor_sync(FULL, d, 8);

    if (valid && odd == 0) {
        float invd = 1.0f / denom;
        *reinterpret_cast<float4*>(&out[node * OUT_DIM + 4 * sub]) =
            make_float4(o0 * invd, o1 * invd, o2 * invd, o3 * invd);
    }
}

extern "C" void kernel_launch(void* const* d_in, const int* in_sizes, int n_in,
                              void* d_out, int out_size)
{
    const float* h    = (const float*)d_in[0];   // [N, 128]
    const float* W    = (const float*)d_in[1];   // [32, 128]
    const float* beta = (const float*)d_in[2];   // [1]
    const int*   src  = (const int*)d_in[3];     // [E]
    float* out = (float*)d_out;

    int N = in_sizes[0] / IN_DIM;                // 100000
    int ntiles = (N + 63) / 64;                  // 1563

    cudaFuncSetAttribute(gemm_wmma_kernel,
                         cudaFuncAttributeMaxDynamicSharedMemorySize,
                         GEMM_SMEM_BYTES);
    gemm_wmma_kernel<<<ntiles, 256, GEMM_SMEM_BYTES>>>(h, W, N);

    int nwarps  = (N + 1) / 2;
    int nblocks = (nwarps + 7) / 8;              // 8 warps / block
    edge_agg_kernel<<<nblocks, 256>>>(beta, src, out, N);
}

// round 16
// speedup vs baseline: 1.0635x; 1.0635x over previous
#include <cuda_runtime.h>
#include <cuda_fp16.h>
#include <mma.h>
#include <math.h>
#include <stdint.h>

using namespace nvcuda;

#define N_NODES   100000
#define DEG       16
#define IN_DIM    128
#define OUT_DIM   32
#define EPS       1e-8f

// scratch (device globals: no allocation allowed in kernel_launch)
__device__ __half2 g_zh[N_NODES * (OUT_DIM / 2)];   // z rows in fp16 (only copy)
__device__ float   g_inorm[N_NODES];                // 1 / max(||z_i||, EPS)

__device__ __forceinline__ float2 h2f(uint32_t u) {
    __half2 h = *reinterpret_cast<__half2*>(&u);
    return __half22float2(h);
}

// ---------------------------------------------------------------------------
// Kernel 1: z = h @ W^T via wmma FP16 (m16n16k16), fp32 accumulate, fused
// inverse row norms (identical to R14 — at HBM floor).
// One CTA per 64-row tile (1563 CTAs), 256 threads = 8 warps, 26.1KB smem.
// ---------------------------------------------------------------------------
#define LDH2 136
#define LDZ  36
#define GEMM_SMEM_BYTES 26112

__global__ __launch_bounds__(256) void gemm_wmma_kernel(
    const float* __restrict__ h, const float* __restrict__ W, int N)
{
    extern __shared__ char smraw[];
    __half* Ws  = reinterpret_cast<__half*>(smraw);           // [32][136]
    __half* hs  = reinterpret_cast<__half*>(smraw + 8704);    // [64][136]
    float*  zsm = reinterpret_cast<float*>(smraw + 8704);     // [64][36] alias

    const int tid  = threadIdx.x;
    const int wid  = tid >> 5;
    const int m0   = (wid & 3) * 16;
    const int n0   = (wid >> 2) * 16;
    const int row0 = blockIdx.x * 64;
    const unsigned FULL = 0xffffffffu;

    // ---- stage W -> fp16 smem ----
    const float4* W4 = reinterpret_cast<const float4*>(W);
    #pragma unroll
    for (int i = 0; i < 4; i++) {
        int f  = tid + i * 256;
        int n  = f >> 5;
        int k4 = f & 31;
        float4 v = __ldg(&W4[n * 32 + k4]);
        __half2 hx[2] = { __floats2half2_rn(v.x, v.y),
                          __floats2half2_rn(v.z, v.w) };
        *reinterpret_cast<uint2*>(&Ws[n * LDH2 + k4 * 4]) =
            *reinterpret_cast<const uint2*>(hx);
    }

    // ---- load 64-row h tile -> fp16 smem ----
    const float4* h4 = reinterpret_cast<const float4*>(h);
    #pragma unroll
    for (int i = 0; i < 8; i++) {
        int f    = tid + i * 256;
        int r    = f >> 5;
        int k4   = f & 31;
        int grow = row0 + r;
        if (grow >= N) grow = N - 1;
        float4 v = __ldg(&h4[grow * 32 + k4]);
        __half2 hx[2] = { __floats2half2_rn(v.x, v.y),
                          __floats2half2_rn(v.z, v.w) };
        *reinterpret_cast<uint2*>(&hs[r * LDH2 + k4 * 4]) =
            *reinterpret_cast<const uint2*>(hx);
    }
    __syncthreads();

    // ---- wmma: 1 m-tile x 1 n-tile x 8 k-steps per warp ----
    wmma::fragment<wmma::accumulator, 16, 16, 16, float> c0;
    wmma::fill_fragment(c0, 0.0f);
    wmma::fragment<wmma::matrix_a, 16, 16, 16, __half, wmma::row_major> a0;
    wmma::fragment<wmma::matrix_b, 16, 16, 16, __half, wmma::col_major> b0;
    #pragma unroll
    for (int ks = 0; ks < 8; ks++) {
        wmma::load_matrix_sync(a0, &hs[m0 * LDH2 + ks * 16], LDH2);
        wmma::load_matrix_sync(b0, &Ws[n0 * LDH2 + ks * 16], LDH2);
        wmma::mma_sync(c0, a0, b0, c0);
    }
    __syncthreads();

    wmma::store_matrix_sync(&zsm[m0 * LDZ + n0], c0, LDZ, wmma::mem_row_major);
    __syncthreads();

    // ---- epilogue: fp16 z (coalesced) + inverse norms ----
    int row = tid >> 2;
    int q   = tid & 3;
    float4 z4[2];
    z4[0] = *reinterpret_cast<const float4*>(&zsm[row * LDZ + q * 8]);
    z4[1] = *reinterpret_cast<const float4*>(&zsm[row * LDZ + q * 8 + 4]);
    float ss = z4[0].x * z4[0].x + z4[0].y * z4[0].y
             + z4[0].z * z4[0].z + z4[0].w * z4[0].w
             + z4[1].x * z4[1].x + z4[1].y * z4[1].y
             + z4[1].z * z4[1].z + z4[1].w * z4[1].w;
    ss += __shfl_xor_sync(FULL, ss, 1);
    ss += __shfl_xor_sync(FULL, ss, 2);
    int grow = row0 + row;
    if (grow < N) {
        __half2 hx[4];
        hx[0] = __floats2half2_rn(z4[0].x, z4[0].y);
        hx[1] = __floats2half2_rn(z4[0].z, z4[0].w);
        hx[2] = __floats2half2_rn(z4[1].x, z4[1].y);
        hx[3] = __floats2half2_rn(z4[1].z, z4[1].w);
        *reinterpret_cast<uint4*>(&g_zh[grow * 16 + q * 4]) =
            *reinterpret_cast<const uint4*>(hx);
        if (q == 0)
            g_inorm[grow] = 1.0f / fmaxf(sqrtf(ss), EPS);
    }
}

// ---------------------------------------------------------------------------
// Kernel 2: per-node cosine attention + softmax + weighted aggregation.
// R14 structure (parity-split half-warp per node, single pack-tree, norm via
// scattered g_inorm), with the dot-partial loop in packed HFMA2 arithmetic
// (4 instr/edge instead of 8). Trees + aggregation remain fp32.
// ---------------------------------------------------------------------------
__global__ __launch_bounds__(256) void edge_agg_kernel(
    const float* __restrict__ beta_p, const int* __restrict__ src,
    float* __restrict__ out, int N)
{
    __shared__ float alpha_sm[8][32];

    const int warp_id = (blockIdx.x * blockDim.x + threadIdx.x) >> 5;
    if (warp_id * 2 >= N) return;

    const int w    = threadIdx.x >> 5;
    const int lane = threadIdx.x & 31;
    const int half = lane >> 4;
    const int hl   = lane & 15;
    const int odd  = (hl >> 3) & 1;
    const int sub  = hl & 7;
    int node = warp_id * 2 + half;
    const bool valid = (node < N);
    if (!valid) node = N - 1;

    const unsigned FULL = 0xffffffffu;
    const float beta = __ldg(beta_p);
    const __half* zh = reinterpret_cast<const __half*>(g_zh);

    // own z chunk: dims 4*sub .. 4*sub+3 (kept packed for HFMA2)
    uint2 zraw = *reinterpret_cast<const uint2*>(zh + node * 32 + 4 * sub);
    __half2 zdh0 = *reinterpret_cast<__half2*>(&zraw.x);
    __half2 zdh1 = *reinterpret_cast<__half2*>(&zraw.y);
    const float inv_nd = g_inorm[node];

    // all 16 src indices (uniform int4 loads)
    const int4* sp = reinterpret_cast<const int4*>(src + node * DEG);
    int4 s0 = __ldg(sp + 0);
    int4 s1 = __ldg(sp + 1);
    int4 s2 = __ldg(sp + 2);
    int4 s3 = __ldg(sp + 3);
    int si[DEG] = { s0.x, s0.y, s0.z, s0.w,  s1.x, s1.y, s1.z, s1.w,
                    s2.x, s2.y, s2.z, s2.w,  s3.x, s3.y, s3.z, s3.w };

    // gather order: item k = edge 2*R3[k] + odd  (R3 = 3-bit bit-reverse)
    constexpr int R3[8] = {0,4,2,6,1,5,3,7};
    int se[8];
    #pragma unroll
    for (int k = 0; k < 8; k++) {
        int e = 2 * R3[k];
        se[k] = odd ? si[e + 1] : si[e];
    }

    // own-edge (2*sub+odd) norm scale
    const int sid_own = __ldg(src + node * DEG + 2 * sub + odd);
    const float cc = __ldg(&g_inorm[sid_own]) * inv_nd;

    // gather: 4 dims of one edge per lane per LDG.64
    uint2 v[8];
    #pragma unroll
    for (int k = 0; k < 8; k++)
        v[k] = *reinterpret_cast<const uint2*>(zh + se[k] * 32 + 4 * sub);

    // per-lane 4-dim partial dots in packed half2 (4 instr/edge)
    float p[8];
    #pragma unroll
    for (int k = 0; k < 8; k++) {
        __half2 vx = *reinterpret_cast<__half2*>(&v[k].x);
        __half2 vy = *reinterpret_cast<__half2*>(&v[k].y);
        __half2 t  = __hfma2(vx, zdh0, __hmul2(vy, zdh1));
        p[k] = __half2float(__hadd(__low2half(t), __high2half(t)));
    }

    // ---- 3-level pack-tree over 8-lane subgroups (14 shfl/warp) ----
    const bool c4 = (sub & 4) != 0;
    const bool c2 = (sub & 2) != 0;
    const bool c1 = (sub & 1) != 0;

    float s[4];
    #pragma unroll
    for (int i = 0; i < 4; i++) {
        float a = p[2 * i]     + __shfl_xor_sync(FULL, p[2 * i], 4);
        float b = p[2 * i + 1] + __shfl_xor_sync(FULL, p[2 * i + 1], 4);
        s[i] = c4 ? b : a;
    }
    float q[2];
    #pragma unroll
    for (int i = 0; i < 2; i++) {
        float a = s[2 * i]     + __shfl_xor_sync(FULL, s[2 * i], 2);
        float b = s[2 * i + 1] + __shfl_xor_sync(FULL, s[2 * i + 1], 2);
        q[i] = c2 ? b : a;
    }
    float ra = q[0] + __shfl_xor_sync(FULL, q[0], 1);
    float rb = q[1] + __shfl_xor_sync(FULL, q[1], 1);
    float dotv = c1 ? rb : ra;         // dot of edge 2*sub+odd

    // softmax weight: exp(beta*cos) (constant -beta cancels; bounded)
    float esc = __expf(beta * (dotv * cc));

    // slot hl = (odd<<3)|sub holds esc of edge 2*sub+odd
    alpha_sm[w][lane] = esc;
    __syncwarp(FULL);

    // read own parity block: slot s holds edge 2s+odd = alpha of v[R3[s]]
    const float4* ap = reinterpret_cast<const float4*>(&alpha_sm[w][lane & 24]);
    float4 A0 = ap[0];
    float4 A1 = ap[1];
    float d = (A0.x + A0.y) + (A0.z + A0.w) + (A1.x + A1.y) + (A1.z + A1.w);

    float o0 = 0.f, o1 = 0.f, o2 = 0.f, o3 = 0.f;
    #define ACC(af, vm) do {                                   \
        float2 va = h2f((vm).x);                               \
        float2 vb = h2f((vm).y);                               \
        o0 = fmaf((af), va.x, o0);  o1 = fmaf((af), va.y, o1); \
        o2 = fmaf((af), vb.x, o2);  o3 = fmaf((af), vb.y, o3); \
    } while (0)
    ACC(A0.x, v[0]);  ACC(A0.y, v[4]);  ACC(A0.z, v[2]);  ACC(A0.w, v[6]);
    ACC(A1.x, v[1]);  ACC(A1.y, v[5]);  ACC(A1.z, v[3]);  ACC(A1.w, v[7]);
    #undef ACC

    // combine parity halves (same sub, other odd)
    o0 += __shfl_xor_sync(FULL, o0, 8);
    o1 += __shfl_xor_sync(FULL, o1, 8);
    o2 += __shfl_xor_sync(FULL, o2, 8);
    o3 += __shfl_xor_sync(FULL, o3, 8);
    float denom = d + __shfl_xor_sync(FULL, d, 8);

    if (valid && odd == 0) {
        float invd = 1.0f / denom;
        *reinterpret_cast<float4*>(&out[node * OUT_DIM + 4 * sub]) =
            make_float4(o0 * invd, o1 * invd, o2 * invd, o3 * invd);
    }
}

extern "C" void kernel_launch(void* const* d_in, const int* in_sizes, int n_in,
                              void* d_out, int out_size)
{
    const float* h    = (const float*)d_in[0];   // [N, 128]
    const float* W    = (const float*)d_in[1];   // [32, 128]
    const float* beta = (const float*)d_in[2];   // [1]
    const int*   src  = (const int*)d_in[3];     // [E]
    float* out = (float*)d_out;

    int N = in_sizes[0] / IN_DIM;                // 100000
    int ntiles = (N + 63) / 64;                  // 1563

    cudaFuncSetAttribute(gemm_wmma_kernel,
                         cudaFuncAttributeMaxDynamicSharedMemorySize,
                         GEMM_SMEM_BYTES);
    gemm_wmma_kernel<<<ntiles, 256, GEMM_SMEM_BYTES>>>(h, W, N);

    int nwarps  = (N + 1) / 2;
    int nblocks = (nwarps + 7) / 8;              // 8 warps / block
    edge_agg_kernel<<<nblocks, 256>>>(beta, src, out, N);
}